// round 2
// baseline (speedup 1.0000x reference)
#include <cuda_runtime.h>
#include <math.h>

#define RES 256
#define W 256
#define H 256
#define MAX_SAMPLES 384
#define TF_RES 128
#define NEAR_T 0.1f
#define FAR_T 100.0f
#define HIT_EPS 1e-3f
#define UNROLL 4
#define BLOCK 128

struct V3 { float x, y, z; };

__device__ __forceinline__ V3 v3(float x, float y, float z) { V3 r; r.x=x; r.y=y; r.z=z; return r; }
__device__ __forceinline__ V3 vadd(V3 a, V3 b) { return v3(a.x+b.x, a.y+b.y, a.z+b.z); }
__device__ __forceinline__ V3 vscale(V3 a, float s) { return v3(a.x*s, a.y*s, a.z*s); }
__device__ __forceinline__ V3 vcross(V3 a, V3 b) {
    return v3(a.y*b.z - a.z*b.y, a.z*b.x - a.x*b.z, a.x*b.y - a.y*b.x);
}
__device__ __forceinline__ V3 vnorm(V3 a) {
    float inv = rsqrtf(a.x*a.x + a.y*a.y + a.z*a.z);
    return vscale(a, inv);
}

__global__ void __launch_bounds__(BLOCK, 8)
raycast_kernel(const float* __restrict__ vol,
               const float* __restrict__ tf,
               const float* __restrict__ cam_in,
               const int*   __restrict__ sr_in,
               float* __restrict__ out)
{
    __shared__ float4 s_tf[TF_RES];
    int tid = threadIdx.x;
    if (tid < TF_RES) s_tf[tid] = reinterpret_cast<const float4*>(tf)[tid];
    __syncthreads();

    int pix = blockIdx.x * BLOCK + tid;
    int w = pix >> 8;          // 0..255
    int h = pix & 255;         // 0..255

    // --- decode sampling rate (robust to int32 or float32 storage) ---
    int raw = sr_in[0];
    float sr;
    if (raw >= 1 && raw <= 4096) {
        sr = (float)raw;
    } else {
        float f = __int_as_float(raw);
        sr = (f > 0.0f && f <= 4096.0f) ? f : 1.0f;
    }
    float inv_sr = 1.0f / sr;
    bool sr_is_one = (sr == 1.0f);

    V3 cam = v3(cam_in[0], cam_in[1], cam_in[2]);

    // camera basis
    V3 fwd = vnorm(v3(-cam.x, -cam.y, -cam.z));
    V3 right = vnorm(v3(-fwd.z, 0.0f, fwd.x));       // cross(fwd, (0,1,0))
    V3 up = vcross(right, fwd);

    const float tanf_half = 0.2679491924311227f;      // tan(15 deg)
    float u = ((w + 0.5f) * (1.0f / (float)W) * 2.0f - 1.0f) * tanf_half;
    float v = ((h + 0.5f) * (1.0f / (float)H) * 2.0f - 1.0f) * tanf_half;

    V3 dir = vnorm(vadd(fwd, vadd(vscale(right, u), vscale(up, v))));

    // ray vs [-1,1]^3
    float ix = 1.0f / dir.x, iy = 1.0f / dir.y, iz = 1.0f / dir.z;
    float tx0 = (-1.0f - cam.x) * ix, tx1 = (1.0f - cam.x) * ix;
    float ty0 = (-1.0f - cam.y) * iy, ty1 = (1.0f - cam.y) * iy;
    float tz0 = (-1.0f - cam.z) * iz, tz1 = (1.0f - cam.z) * iz;
    float tmin = fmaxf(fmaxf(fminf(tx0, tx1), fminf(ty0, ty1)), fminf(tz0, tz1));
    float tmax = fminf(fminf(fmaxf(tx0, tx1), fmaxf(ty0, ty1)), fmaxf(tz0, tz1));
    bool hit = (tmax >= 0.0f) && (tmin <= tmax);

    float rr = 0.0f, gg = 0.0f, bb = 0.0f, acc = 0.0f;
    float depth = 1.0f;

    if (hit) {
        float entry = fmaxf(tmin, NEAR_T);
        float dist = fmaxf(tmax - entry, 0.0f);
        float ns = ceilf(dist * 0.5f * (float)RES * sr);
        ns = fminf(fmaxf(ns, 1.0f), (float)MAX_SAMPLES);
        float step = dist / ns;
        int n = (int)ns;

        float T = 1.0f;
        bool any_hit = false;
        float t_first = 0.0f;
        bool alive = true;

        for (int k0 = 0; k0 < n && alive; k0 += UNROLL) {
            // ---- phase 1: compute 4 sample positions, issue all 32 loads ----
            float inten[UNROLL];
            {
                float c000[UNROLL], c001[UNROLL], c010[UNROLL], c011[UNROLL];
                float c100[UNROLL], c101[UNROLL], c110[UNROLL], c111[UNROLL];
                float fx[UNROLL], fy[UNROLL], fz[UNROLL];
                #pragma unroll
                for (int uu = 0; uu < UNROLL; uu++) {
                    float t = entry + ((float)(k0 + uu) + 0.5f) * step;
                    float px = cam.x + t * dir.x;
                    float py = cam.y + t * dir.y;
                    float pz = cam.z + t * dir.z;
                    float qx = fminf(fmaxf((px * 0.5f + 0.5f) * 255.0f, 0.0f), 255.0f);
                    float qy = fminf(fmaxf((py * 0.5f + 0.5f) * 255.0f, 0.0f), 255.0f);
                    float qz = fminf(fmaxf((pz * 0.5f + 0.5f) * 255.0f, 0.0f), 255.0f);
                    int x0 = (int)qx, y0 = (int)qy, z0 = (int)qz;
                    fx[uu] = qx - (float)x0;
                    fy[uu] = qy - (float)y0;
                    fz[uu] = qz - (float)z0;
                    int dx = (x0 < RES - 1) ? RES * RES : 0;
                    int dy = (y0 < RES - 1) ? RES : 0;
                    int dz = (z0 < RES - 1) ? 1 : 0;
                    int base = (((x0 << 8) + y0) << 8) + z0;
                    c000[uu] = __ldg(vol + base);
                    c001[uu] = __ldg(vol + base + dz);
                    c010[uu] = __ldg(vol + base + dy);
                    c011[uu] = __ldg(vol + base + dy + dz);
                    c100[uu] = __ldg(vol + base + dx);
                    c101[uu] = __ldg(vol + base + dx + dz);
                    c110[uu] = __ldg(vol + base + dx + dy);
                    c111[uu] = __ldg(vol + base + dx + dy + dz);
                }
                #pragma unroll
                for (int uu = 0; uu < UNROLL; uu++) {
                    float c00 = c000[uu] + fx[uu] * (c100[uu] - c000[uu]);
                    float c10 = c010[uu] + fx[uu] * (c110[uu] - c010[uu]);
                    float c01 = c001[uu] + fx[uu] * (c101[uu] - c001[uu]);
                    float c11 = c011[uu] + fx[uu] * (c111[uu] - c011[uu]);
                    float c0 = c00 + fy[uu] * (c10 - c00);
                    float c1 = c01 + fy[uu] * (c11 - c01);
                    inten[uu] = c0 + fz[uu] * (c1 - c0);
                }
            }

            // ---- phase 2: TF lookup + sequential composite ----
            #pragma unroll
            for (int uu = 0; uu < UNROLL; uu++) {
                int kk = k0 + uu;
                if (kk < n && alive) {
                    float xi = fminf(fmaxf(inten[uu], 0.0f), 1.0f) * (float)(TF_RES - 1);
                    int l = (int)xi;
                    float f = xi - (float)l;
                    int hi2 = min(l + 1, TF_RES - 1);
                    float4 ca = s_tf[l];
                    float4 cb = s_tf[hi2];
                    float cr = ca.x + f * (cb.x - ca.x);
                    float cg = ca.y + f * (cb.y - ca.y);
                    float cbv = ca.z + f * (cb.z - ca.z);
                    float a = ca.w + f * (cb.w - ca.w);

                    if (!sr_is_one) a = 1.0f - powf(1.0f - a, inv_sr);

                    float wgt = T * a;
                    rr += wgt * cr;
                    gg += wgt * cg;
                    bb += wgt * cbv;
                    acc += wgt;
                    T *= (1.0f - a);

                    if (!any_hit && a > HIT_EPS) {
                        any_hit = true;
                        t_first = entry + ((float)kk + 0.5f) * step;
                    }
                    // Early termination: remaining contribution bounded by T<1e-6;
                    // first-hit is provably already resolved at this point.
                    if (T < 1e-6f) alive = false;
                }
            }
        }

        if (any_hit) depth = (t_first - NEAR_T) / (FAR_T - NEAR_T);
    }

    float* o = out + (size_t)pix * 5;
    o[0] = rr;
    o[1] = gg;
    o[2] = bb;
    o[3] = acc;
    o[4] = depth;
}

extern "C" void kernel_launch(void* const* d_in, const int* in_sizes, int n_in,
                              void* d_out, int out_size)
{
    const float* vol = (const float*)d_in[0];
    const float* tf  = (const float*)d_in[1];
    const float* cam = (const float*)d_in[2];
    const int*   sr  = (const int*)d_in[3];
    float* out = (float*)d_out;
    raycast_kernel<<<(W * H) / BLOCK, BLOCK>>>(vol, tf, cam, sr, out);
}

// round 3
// speedup vs baseline: 1.4787x; 1.4787x over previous
#include <cuda_runtime.h>
#include <math.h>

#define RES 256
#define W 256
#define H 256
#define MAX_SAMPLES 384
#define TF_RES 128
#define NEAR_T 0.1f
#define FAR_T 100.0f
#define HIT_EPS 1e-3f
#define BLOCK 128

struct V3 { float x, y, z; };

__device__ __forceinline__ V3 v3(float x, float y, float z) { V3 r; r.x=x; r.y=y; r.z=z; return r; }
__device__ __forceinline__ V3 vadd(V3 a, V3 b) { return v3(a.x+b.x, a.y+b.y, a.z+b.z); }
__device__ __forceinline__ V3 vscale(V3 a, float s) { return v3(a.x*s, a.y*s, a.z*s); }
__device__ __forceinline__ V3 vcross(V3 a, V3 b) {
    return v3(a.y*b.z - a.z*b.y, a.z*b.x - a.x*b.z, a.x*b.y - a.y*b.x);
}
__device__ __forceinline__ V3 vnorm(V3 a) {
    float inv = rsqrtf(a.x*a.x + a.y*a.y + a.z*a.z);
    return vscale(a, inv);
}

__global__ void __launch_bounds__(BLOCK, 8)
raycast_kernel(const float* __restrict__ vol,
               const float* __restrict__ tf,
               const float* __restrict__ cam_in,
               const int*   __restrict__ sr_in,
               float* __restrict__ out)
{
    __shared__ float4 s_tf[TF_RES];
    int tid = threadIdx.x;
    if (tid < TF_RES) s_tf[tid] = reinterpret_cast<const float4*>(tf)[tid];
    __syncthreads();

    // ---- pixel mapping: warp tile = 8h x 4w, block tile = 16h x 8w ----
    // Lanes within a warp stay spatially compact in BOTH image axes so their
    // volume addresses share 128B lines (y-stride is 1KB; minimizing the
    // warp's y-extent minimizes distinct lines per LDG).
    int lane = tid & 31;
    int warp = tid >> 5;
    int h_in = lane & 7;             // 0..7
    int w_in = lane >> 3;            // 0..3
    int warp_h = (warp & 1) << 3;    // 0 or 8
    int warp_w = (warp >> 1) << 2;   // 0 or 4
    int bx = blockIdx.x;             // 0..511
    int tile_h = (bx & 15) << 4;     // 16 tiles of 16 in h
    int tile_w = (bx >> 4) << 3;     // 32 tiles of 8 in w
    int h = tile_h + warp_h + h_in;
    int w = tile_w + warp_w + w_in;

    // --- decode sampling rate (robust to int32 or float32 storage) ---
    int raw = sr_in[0];
    float sr;
    if (raw >= 1 && raw <= 4096) {
        sr = (float)raw;
    } else {
        float f = __int_as_float(raw);
        sr = (f > 0.0f && f <= 4096.0f) ? f : 1.0f;
    }
    float inv_sr = 1.0f / sr;
    bool sr_is_one = (sr == 1.0f);

    V3 cam = v3(cam_in[0], cam_in[1], cam_in[2]);

    // camera basis
    V3 fwd = vnorm(v3(-cam.x, -cam.y, -cam.z));
    V3 right = vnorm(v3(-fwd.z, 0.0f, fwd.x));       // cross(fwd, (0,1,0))
    V3 up = vcross(right, fwd);

    const float tanf_half = 0.2679491924311227f;      // tan(15 deg)
    float u = ((w + 0.5f) * (2.0f / (float)W) - 1.0f) * tanf_half;
    float v = ((h + 0.5f) * (2.0f / (float)H) - 1.0f) * tanf_half;

    V3 dir = vnorm(vadd(fwd, vadd(vscale(right, u), vscale(up, v))));

    // ray vs [-1,1]^3
    float ix = 1.0f / dir.x, iy = 1.0f / dir.y, iz = 1.0f / dir.z;
    float tx0 = (-1.0f - cam.x) * ix, tx1 = (1.0f - cam.x) * ix;
    float ty0 = (-1.0f - cam.y) * iy, ty1 = (1.0f - cam.y) * iy;
    float tz0 = (-1.0f - cam.z) * iz, tz1 = (1.0f - cam.z) * iz;
    float tmin = fmaxf(fmaxf(fminf(tx0, tx1), fminf(ty0, ty1)), fminf(tz0, tz1));
    float tmax = fminf(fminf(fmaxf(tx0, tx1), fmaxf(ty0, ty1)), fmaxf(tz0, tz1));
    bool hit = (tmax >= 0.0f) && (tmin <= tmax);

    float rr = 0.0f, gg = 0.0f, bb = 0.0f, acc = 0.0f;
    float depth = 1.0f;

    if (hit) {
        float entry = fmaxf(tmin, NEAR_T);
        float dist = fmaxf(tmax - entry, 0.0f);
        float ns = ceilf(dist * 0.5f * (float)RES * sr);
        ns = fminf(fmaxf(ns, 1.0f), (float)MAX_SAMPLES);
        float step = dist / ns;
        int n = (int)ns;

        float T = 1.0f;
        bool any_hit = false;
        float t_first = 0.0f;

        for (int k = 0; k < n; k++) {
            float t = entry + ((float)k + 0.5f) * step;
            float px = cam.x + t * dir.x;
            float py = cam.y + t * dir.y;
            float pz = cam.z + t * dir.z;
            float qx = fminf(fmaxf((px * 0.5f + 0.5f) * 255.0f, 0.0f), 255.0f);
            float qy = fminf(fmaxf((py * 0.5f + 0.5f) * 255.0f, 0.0f), 255.0f);
            float qz = fminf(fmaxf((pz * 0.5f + 0.5f) * 255.0f, 0.0f), 255.0f);
            int x0 = (int)qx, y0 = (int)qy, z0 = (int)qz;
            float fx = qx - (float)x0;
            float fy = qy - (float)y0;
            float fz = qz - (float)z0;
            int dx = (x0 < RES - 1) ? RES * RES : 0;
            int dy = (y0 < RES - 1) ? RES : 0;
            int dz = (z0 < RES - 1) ? 1 : 0;
            int base = (((x0 << 8) + y0) << 8) + z0;

            float c000 = __ldg(vol + base);
            float c001 = __ldg(vol + base + dz);
            float c010 = __ldg(vol + base + dy);
            float c011 = __ldg(vol + base + dy + dz);
            float c100 = __ldg(vol + base + dx);
            float c101 = __ldg(vol + base + dx + dz);
            float c110 = __ldg(vol + base + dx + dy);
            float c111 = __ldg(vol + base + dx + dy + dz);

            float c00 = c000 + fx * (c100 - c000);
            float c10 = c010 + fx * (c110 - c010);
            float c01 = c001 + fx * (c101 - c001);
            float c11 = c011 + fx * (c111 - c011);
            float c0 = c00 + fy * (c10 - c00);
            float c1 = c01 + fy * (c11 - c01);
            float intensity = c0 + fz * (c1 - c0);

            float xi = fminf(fmaxf(intensity, 0.0f), 1.0f) * (float)(TF_RES - 1);
            int l = (int)xi;
            float f = xi - (float)l;
            int hi2 = min(l + 1, TF_RES - 1);
            float4 ca = s_tf[l];
            float4 cb = s_tf[hi2];
            float cr = ca.x + f * (cb.x - ca.x);
            float cg = ca.y + f * (cb.y - ca.y);
            float cbv = ca.z + f * (cb.z - ca.z);
            float a = ca.w + f * (cb.w - ca.w);

            if (!sr_is_one) a = 1.0f - powf(1.0f - a, inv_sr);

            float wgt = T * a;
            rr += wgt * cr;
            gg += wgt * cg;
            bb += wgt * cbv;
            acc += wgt;
            T *= (1.0f - a);

            if (!any_hit && a > HIT_EPS) { any_hit = true; t_first = t; }
            // Early termination: remaining contribution bounded by T < 1e-5.
            // First-hit depth provably resolved: if all a<=1e-3 then
            // T >= 0.999^384 = 0.68 >> 1e-5, so T<1e-5 implies a hit occurred.
            if (T < 1e-5f) break;
        }

        if (any_hit) depth = (t_first - NEAR_T) / (FAR_T - NEAR_T);
    }

    float* o = out + ((size_t)w * H + h) * 5;
    o[0] = rr;
    o[1] = gg;
    o[2] = bb;
    o[3] = acc;
    o[4] = depth;
}

extern "C" void kernel_launch(void* const* d_in, const int* in_sizes, int n_in,
                              void* d_out, int out_size)
{
    const float* vol = (const float*)d_in[0];
    const float* tf  = (const float*)d_in[1];
    const float* cam = (const float*)d_in[2];
    const int*   sr  = (const int*)d_in[3];
    float* out = (float*)d_out;
    raycast_kernel<<<(W * H) / BLOCK, BLOCK>>>(vol, tf, cam, sr, out);
}

// round 4
// speedup vs baseline: 1.4809x; 1.0015x over previous
#include <cuda_runtime.h>
#include <math.h>

#define RES 256
#define W 256
#define H 256
#define MAX_SAMPLES 384
#define TF_RES 128
#define NEAR_T 0.1f
#define FAR_T 100.0f
#define HIT_EPS 1e-3f
#define BLOCK 128

struct V3 { float x, y, z; };

__device__ __forceinline__ V3 v3(float x, float y, float z) { V3 r; r.x=x; r.y=y; r.z=z; return r; }
__device__ __forceinline__ V3 vadd(V3 a, V3 b) { return v3(a.x+b.x, a.y+b.y, a.z+b.z); }
__device__ __forceinline__ V3 vscale(V3 a, float s) { return v3(a.x*s, a.y*s, a.z*s); }
__device__ __forceinline__ V3 vcross(V3 a, V3 b) {
    return v3(a.y*b.z - a.z*b.y, a.z*b.x - a.x*b.z, a.x*b.y - a.y*b.x);
}
__device__ __forceinline__ V3 vnorm(V3 a) {
    float inv = rsqrtf(a.x*a.x + a.y*a.y + a.z*a.z);
    return vscale(a, inv);
}

// Sample the volume trilinearly at march index k; returns interpolated intensity.
// All loads for one sample are issued back-to-back (independent addresses).
__device__ __forceinline__ float sample_vol(const float* __restrict__ vol,
                                            V3 cam, V3 dir,
                                            float entry, float step, int k)
{
    float t = entry + ((float)k + 0.5f) * step;
    float px = cam.x + t * dir.x;
    float py = cam.y + t * dir.y;
    float pz = cam.z + t * dir.z;
    float qx = fminf(fmaxf((px * 0.5f + 0.5f) * 255.0f, 0.0f), 255.0f);
    float qy = fminf(fmaxf((py * 0.5f + 0.5f) * 255.0f, 0.0f), 255.0f);
    float qz = fminf(fmaxf((pz * 0.5f + 0.5f) * 255.0f, 0.0f), 255.0f);
    int x0 = (int)qx, y0 = (int)qy, z0 = (int)qz;
    float fx = qx - (float)x0;
    float fy = qy - (float)y0;
    float fz = qz - (float)z0;
    int dx = (x0 < RES - 1) ? RES * RES : 0;
    int dy = (y0 < RES - 1) ? RES : 0;
    int dz = (z0 < RES - 1) ? 1 : 0;
    int base = (((x0 << 8) + y0) << 8) + z0;

    float c000 = __ldg(vol + base);
    float c001 = __ldg(vol + base + dz);
    float c010 = __ldg(vol + base + dy);
    float c011 = __ldg(vol + base + dy + dz);
    float c100 = __ldg(vol + base + dx);
    float c101 = __ldg(vol + base + dx + dz);
    float c110 = __ldg(vol + base + dx + dy);
    float c111 = __ldg(vol + base + dx + dy + dz);

    float c00 = c000 + fx * (c100 - c000);
    float c10 = c010 + fx * (c110 - c010);
    float c01 = c001 + fx * (c101 - c001);
    float c11 = c011 + fx * (c111 - c011);
    float c0 = c00 + fy * (c10 - c00);
    float c1 = c01 + fy * (c11 - c01);
    return c0 + fz * (c1 - c0);
}

__global__ void __launch_bounds__(BLOCK, 8)
raycast_kernel(const float* __restrict__ vol,
               const float* __restrict__ tf,
               const float* __restrict__ cam_in,
               const int*   __restrict__ sr_in,
               float* __restrict__ out)
{
    __shared__ float4 s_tf[TF_RES];
    int tid = threadIdx.x;
    if (tid < TF_RES) s_tf[tid] = reinterpret_cast<const float4*>(tf)[tid];
    __syncthreads();

    // ---- pixel mapping: warp tile = 8h x 4w, block tile = 16h x 8w ----
    int lane = tid & 31;
    int warp = tid >> 5;
    int h_in = lane & 7;
    int w_in = lane >> 3;
    int warp_h = (warp & 1) << 3;
    int warp_w = (warp >> 1) << 2;
    int bx = blockIdx.x;
    int tile_h = (bx & 15) << 4;
    int tile_w = (bx >> 4) << 3;
    int h = tile_h + warp_h + h_in;
    int w = tile_w + warp_w + w_in;

    // --- decode sampling rate (robust to int32 or float32 storage) ---
    int raw = sr_in[0];
    float sr;
    if (raw >= 1 && raw <= 4096) {
        sr = (float)raw;
    } else {
        float f = __int_as_float(raw);
        sr = (f > 0.0f && f <= 4096.0f) ? f : 1.0f;
    }
    float inv_sr = 1.0f / sr;
    bool sr_is_one = (sr == 1.0f);

    V3 cam = v3(cam_in[0], cam_in[1], cam_in[2]);

    V3 fwd = vnorm(v3(-cam.x, -cam.y, -cam.z));
    V3 right = vnorm(v3(-fwd.z, 0.0f, fwd.x));
    V3 up = vcross(right, fwd);

    const float tanf_half = 0.2679491924311227f;      // tan(15 deg)
    float u = ((w + 0.5f) * (2.0f / (float)W) - 1.0f) * tanf_half;
    float v = ((h + 0.5f) * (2.0f / (float)H) - 1.0f) * tanf_half;

    V3 dir = vnorm(vadd(fwd, vadd(vscale(right, u), vscale(up, v))));

    float ix = 1.0f / dir.x, iy = 1.0f / dir.y, iz = 1.0f / dir.z;
    float tx0 = (-1.0f - cam.x) * ix, tx1 = (1.0f - cam.x) * ix;
    float ty0 = (-1.0f - cam.y) * iy, ty1 = (1.0f - cam.y) * iy;
    float tz0 = (-1.0f - cam.z) * iz, tz1 = (1.0f - cam.z) * iz;
    float tmin = fmaxf(fmaxf(fminf(tx0, tx1), fminf(ty0, ty1)), fminf(tz0, tz1));
    float tmax = fminf(fminf(fmaxf(tx0, tx1), fmaxf(ty0, ty1)), fmaxf(tz0, tz1));
    bool hit = (tmax >= 0.0f) && (tmin <= tmax);

    float rr = 0.0f, gg = 0.0f, bb = 0.0f, acc = 0.0f;
    float depth = 1.0f;

    if (hit) {
        float entry = fmaxf(tmin, NEAR_T);
        float dist = fmaxf(tmax - entry, 0.0f);
        float ns = ceilf(dist * 0.5f * (float)RES * sr);
        ns = fminf(fmaxf(ns, 1.0f), (float)MAX_SAMPLES);
        float step = dist / ns;
        int n = (int)ns;

        float T = 1.0f;
        bool any_hit = false;
        float t_first = 0.0f;

        for (int k0 = 0; k0 < n; k0 += 2) {
            // Issue both samples' loads before either composite: 16 independent
            // LDGs per branch resolution instead of 8 (halves exposed latency).
            float inten0 = sample_vol(vol, cam, dir, entry, step, k0);
            float inten1 = sample_vol(vol, cam, dir, entry, step, k0 + 1);

            // ---- composite sample k0 (always valid) ----
            {
                float xi = fminf(fmaxf(inten0, 0.0f), 1.0f) * (float)(TF_RES - 1);
                int l = (int)xi;
                float f = xi - (float)l;
                int hi2 = min(l + 1, TF_RES - 1);
                float4 ca = s_tf[l];
                float4 cb = s_tf[hi2];
                float a = ca.w + f * (cb.w - ca.w);
                if (!sr_is_one) a = 1.0f - powf(1.0f - a, inv_sr);
                float wgt = T * a;
                rr += wgt * (ca.x + f * (cb.x - ca.x));
                gg += wgt * (ca.y + f * (cb.y - ca.y));
                bb += wgt * (ca.z + f * (cb.z - ca.z));
                acc += wgt;
                T *= (1.0f - a);
                if (!any_hit && a > HIT_EPS) {
                    any_hit = true;
                    t_first = entry + ((float)k0 + 0.5f) * step;
                }
            }
            // ---- composite sample k0+1 (guard odd n and post-exit) ----
            if (k0 + 1 < n && T >= 1e-5f) {
                float xi = fminf(fmaxf(inten1, 0.0f), 1.0f) * (float)(TF_RES - 1);
                int l = (int)xi;
                float f = xi - (float)l;
                int hi2 = min(l + 1, TF_RES - 1);
                float4 ca = s_tf[l];
                float4 cb = s_tf[hi2];
                float a = ca.w + f * (cb.w - ca.w);
                if (!sr_is_one) a = 1.0f - powf(1.0f - a, inv_sr);
                float wgt = T * a;
                rr += wgt * (ca.x + f * (cb.x - ca.x));
                gg += wgt * (ca.y + f * (cb.y - ca.y));
                bb += wgt * (ca.z + f * (cb.z - ca.z));
                acc += wgt;
                T *= (1.0f - a);
                if (!any_hit && a > HIT_EPS) {
                    any_hit = true;
                    t_first = entry + ((float)(k0 + 1) + 0.5f) * step;
                }
            }
            // Early termination: remaining contribution bounded by T < 1e-5.
            // First-hit depth provably resolved before T can reach 1e-5
            // (all a<=1e-3 over 384 samples keeps T >= 0.68).
            if (T < 1e-5f) break;
        }

        if (any_hit) depth = (t_first - NEAR_T) / (FAR_T - NEAR_T);
    }

    float* o = out + ((size_t)w * H + h) * 5;
    o[0] = rr;
    o[1] = gg;
    o[2] = bb;
    o[3] = acc;
    o[4] = depth;
}

extern "C" void kernel_launch(void* const* d_in, const int* in_sizes, int n_in,
                              void* d_out, int out_size)
{
    const float* vol = (const float*)d_in[0];
    const float* tf  = (const float*)d_in[1];
    const float* cam = (const float*)d_in[2];
    const int*   sr  = (const int*)d_in[3];
    float* out = (float*)d_out;
    raycast_kernel<<<(W * H) / BLOCK, BLOCK>>>(vol, tf, cam, sr, out);
}

// round 5
// speedup vs baseline: 1.6167x; 1.0917x over previous
#include <cuda_runtime.h>
#include <math.h>

#define RES 256
#define W 256
#define H 256
#define MAX_SAMPLES 384
#define TF_RES 128
#define NEAR_T 0.1f
#define FAR_T 100.0f
#define HIT_EPS 1e-3f
#define BLOCK 256

struct V3 { float x, y, z; };

__device__ __forceinline__ V3 v3(float x, float y, float z) { V3 r; r.x=x; r.y=y; r.z=z; return r; }
__device__ __forceinline__ V3 vadd(V3 a, V3 b) { return v3(a.x+b.x, a.y+b.y, a.z+b.z); }
__device__ __forceinline__ V3 vscale(V3 a, float s) { return v3(a.x*s, a.y*s, a.z*s); }
__device__ __forceinline__ V3 vcross(V3 a, V3 b) {
    return v3(a.y*b.z - a.z*b.y, a.z*b.x - a.x*b.z, a.x*b.y - a.y*b.x);
}
__device__ __forceinline__ V3 vnorm(V3 a) {
    float inv = rsqrtf(a.x*a.x + a.y*a.y + a.z*a.z);
    return vscale(a, inv);
}

__device__ __forceinline__ float sample_vol(const float* __restrict__ vol,
                                            V3 cam, V3 dir, float t)
{
    float px = cam.x + t * dir.x;
    float py = cam.y + t * dir.y;
    float pz = cam.z + t * dir.z;
    float qx = fminf(fmaxf((px * 0.5f + 0.5f) * 255.0f, 0.0f), 255.0f);
    float qy = fminf(fmaxf((py * 0.5f + 0.5f) * 255.0f, 0.0f), 255.0f);
    float qz = fminf(fmaxf((pz * 0.5f + 0.5f) * 255.0f, 0.0f), 255.0f);
    int x0 = (int)qx, y0 = (int)qy, z0 = (int)qz;
    float fx = qx - (float)x0;
    float fy = qy - (float)y0;
    float fz = qz - (float)z0;
    int dx = (x0 < RES - 1) ? RES * RES : 0;
    int dy = (y0 < RES - 1) ? RES : 0;
    int dz = (z0 < RES - 1) ? 1 : 0;
    int base = (((x0 << 8) + y0) << 8) + z0;

    float c000 = __ldg(vol + base);
    float c001 = __ldg(vol + base + dz);
    float c010 = __ldg(vol + base + dy);
    float c011 = __ldg(vol + base + dy + dz);
    float c100 = __ldg(vol + base + dx);
    float c101 = __ldg(vol + base + dx + dz);
    float c110 = __ldg(vol + base + dx + dy);
    float c111 = __ldg(vol + base + dx + dy + dz);

    float c00 = c000 + fx * (c100 - c000);
    float c10 = c010 + fx * (c110 - c010);
    float c01 = c001 + fx * (c101 - c001);
    float c11 = c011 + fx * (c111 - c011);
    float c0 = c00 + fy * (c10 - c00);
    float c1 = c01 + fy * (c11 - c01);
    return c0 + fz * (c1 - c0);
}

__global__ void __launch_bounds__(BLOCK, 4)
raycast_kernel(const float* __restrict__ vol,
               const float* __restrict__ tf,
               const float* __restrict__ cam_in,
               const int*   __restrict__ sr_in,
               float* __restrict__ out)
{
    __shared__ float4 s_tf[TF_RES];
    int tid = threadIdx.x;
    if (tid < TF_RES) s_tf[tid] = reinterpret_cast<const float4*>(tf)[tid];
    __syncthreads();

    // ---- 2 lanes per ray. Warp = 16 rays in a 4h x 4w tile. ----
    // Block = 8 warps arranged 4 in h x 2 in w -> block tile 16h x 8w.
    int lane = tid & 31;
    int warp = tid >> 5;
    int sub  = lane & 1;              // 0: even samples, 1: odd samples
    int rid  = lane >> 1;             // ray index within warp (0..15)
    int h_in = rid & 3;
    int w_in = rid >> 2;
    int warp_h = (warp & 3) << 2;
    int warp_w = (warp >> 2) << 2;
    int bx = blockIdx.x;              // 0..511
    int tile_h = (bx & 15) << 4;
    int tile_w = (bx >> 4) << 3;
    int h = tile_h + warp_h + h_in;
    int w = tile_w + warp_w + w_in;

    // --- decode sampling rate (robust to int32 or float32 storage) ---
    int raw = sr_in[0];
    float sr;
    if (raw >= 1 && raw <= 4096) {
        sr = (float)raw;
    } else {
        float f = __int_as_float(raw);
        sr = (f > 0.0f && f <= 4096.0f) ? f : 1.0f;
    }
    float inv_sr = 1.0f / sr;
    bool sr_is_one = (sr == 1.0f);

    V3 cam = v3(cam_in[0], cam_in[1], cam_in[2]);

    V3 fwd = vnorm(v3(-cam.x, -cam.y, -cam.z));
    V3 right = vnorm(v3(-fwd.z, 0.0f, fwd.x));
    V3 up = vcross(right, fwd);

    const float tanf_half = 0.2679491924311227f;      // tan(15 deg)
    float u = ((w + 0.5f) * (2.0f / (float)W) - 1.0f) * tanf_half;
    float v = ((h + 0.5f) * (2.0f / (float)H) - 1.0f) * tanf_half;

    V3 dir = vnorm(vadd(fwd, vadd(vscale(right, u), vscale(up, v))));

    float ix = 1.0f / dir.x, iy = 1.0f / dir.y, iz = 1.0f / dir.z;
    float tx0 = (-1.0f - cam.x) * ix, tx1 = (1.0f - cam.x) * ix;
    float ty0 = (-1.0f - cam.y) * iy, ty1 = (1.0f - cam.y) * iy;
    float tz0 = (-1.0f - cam.z) * iz, tz1 = (1.0f - cam.z) * iz;
    float tmin = fmaxf(fmaxf(fminf(tx0, tx1), fminf(ty0, ty1)), fminf(tz0, tz1));
    float tmax = fminf(fminf(fmaxf(tx0, tx1), fmaxf(ty0, ty1)), fmaxf(tz0, tz1));
    bool hit = (tmax >= 0.0f) && (tmin <= tmax);

    float rr = 0.0f, gg = 0.0f, bb = 0.0f, acc = 0.0f;
    float depth = 1.0f;

    if (hit) {
        float entry = fmaxf(tmin, NEAR_T);
        float dist = fmaxf(tmax - entry, 0.0f);
        float ns = ceilf(dist * 0.5f * (float)RES * sr);
        ns = fminf(fmaxf(ns, 1.0f), (float)MAX_SAMPLES);
        float step = dist / ns;
        int n = (int)ns;

        float T = 1.0f;              // replicated across the lane pair
        bool any_hit = false;
        float t_first = 0.0f;

        for (int k0 = 0; k0 < n; k0 += 2) {
            int k = k0 + sub;        // this lane's sample index
            float t = entry + ((float)k + 0.5f) * step;

            // ---- parallel across the lane pair: sample + TF ----
            float inten = sample_vol(vol, cam, dir, t);
            float xi = fminf(fmaxf(inten, 0.0f), 1.0f) * (float)(TF_RES - 1);
            int l = (int)xi;
            float f = xi - (float)l;
            int hi2 = min(l + 1, TF_RES - 1);
            float4 ca = s_tf[l];
            float4 cb = s_tf[hi2];
            float mcr = ca.x + f * (cb.x - ca.x);
            float mcg = ca.y + f * (cb.y - ca.y);
            float mcb = ca.z + f * (cb.z - ca.z);
            float ma  = ca.w + f * (cb.w - ca.w);
            if (!sr_is_one) ma = 1.0f - powf(1.0f - ma, inv_sr);
            if (k >= n) ma = 0.0f;   // odd-n guard: sample k0+1 invalid

            // ---- exchange partner's (a, rgb) ----
            float oa  = __shfl_xor_sync(0xFFFFFFFFu, ma,  1);
            float ocr = __shfl_xor_sync(0xFFFFFFFFu, mcr, 1);
            float ocg = __shfl_xor_sync(0xFFFFFFFFu, mcg, 1);
            float ocb = __shfl_xor_sync(0xFFFFFFFFu, mcb, 1);

            // order: even-sample first (matches sequential reference)
            float a0  = sub ? oa  : ma;
            float cr0 = sub ? ocr : mcr;
            float cg0 = sub ? ocg : mcg;
            float cb0 = sub ? ocb : mcb;
            float a1  = sub ? ma  : oa;
            float cr1 = sub ? mcr : ocr;
            float cg1 = sub ? mcg : ocg;
            float cb1 = sub ? mcb : ocb;

            // ---- replicated sequential composite (identical in both lanes) ----
            float w0 = T * a0;
            rr += w0 * cr0;
            gg += w0 * cg0;
            bb += w0 * cb0;
            acc += w0;
            float Tm = T * (1.0f - a0);
            float w1 = Tm * a1;
            rr += w1 * cr1;
            gg += w1 * cg1;
            bb += w1 * cb1;
            acc += w1;
            T = Tm * (1.0f - a1);

            if (!any_hit) {
                if (a0 > HIT_EPS) {
                    any_hit = true;
                    t_first = entry + ((float)k0 + 0.5f) * step;
                } else if (a1 > HIT_EPS) {
                    any_hit = true;
                    t_first = entry + ((float)(k0 + 1) + 0.5f) * step;
                }
            }
            // Early termination: remaining contribution bounded by T < 1e-5.
            // First-hit provably resolved before T reaches 1e-5
            // (all a<=1e-3 over 384 samples keeps T >= 0.68).
            if (T < 1e-5f) break;
        }

        if (any_hit) depth = (t_first - NEAR_T) / (FAR_T - NEAR_T);
    }

    if (sub == 0) {
        float* o = out + ((size_t)w * H + h) * 5;
        o[0] = rr;
        o[1] = gg;
        o[2] = bb;
        o[3] = acc;
        o[4] = depth;
    }
}

extern "C" void kernel_launch(void* const* d_in, const int* in_sizes, int n_in,
                              void* d_out, int out_size)
{
    const float* vol = (const float*)d_in[0];
    const float* tf  = (const float*)d_in[1];
    const float* cam = (const float*)d_in[2];
    const int*   sr  = (const int*)d_in[3];
    float* out = (float*)d_out;
    // 2 threads per ray: 131072 threads total
    raycast_kernel<<<(W * H * 2) / BLOCK, BLOCK>>>(vol, tf, cam, sr, out);
}

// round 6
// speedup vs baseline: 1.6782x; 1.0381x over previous
#include <cuda_runtime.h>
#include <math.h>

#define RES 256
#define W 256
#define H 256
#define MAX_SAMPLES 384
#define TF_RES 128
#define NEAR_T 0.1f
#define FAR_T 100.0f
#define HIT_EPS 1e-3f
#define BLOCK 256

struct V3 { float x, y, z; };

__device__ __forceinline__ V3 v3(float x, float y, float z) { V3 r; r.x=x; r.y=y; r.z=z; return r; }
__device__ __forceinline__ V3 vadd(V3 a, V3 b) { return v3(a.x+b.x, a.y+b.y, a.z+b.z); }
__device__ __forceinline__ V3 vscale(V3 a, float s) { return v3(a.x*s, a.y*s, a.z*s); }
__device__ __forceinline__ V3 vcross(V3 a, V3 b) {
    return v3(a.y*b.z - a.z*b.y, a.z*b.x - a.x*b.z, a.x*b.y - a.y*b.x);
}
__device__ __forceinline__ V3 vnorm(V3 a) {
    float inv = rsqrtf(a.x*a.x + a.y*a.y + a.z*a.z);
    return vscale(a, inv);
}

__device__ __forceinline__ float sample_vol(const float* __restrict__ vol,
                                            V3 cam, V3 dir, float t)
{
    float px = cam.x + t * dir.x;
    float py = cam.y + t * dir.y;
    float pz = cam.z + t * dir.z;
    float qx = fminf(fmaxf((px * 0.5f + 0.5f) * 255.0f, 0.0f), 255.0f);
    float qy = fminf(fmaxf((py * 0.5f + 0.5f) * 255.0f, 0.0f), 255.0f);
    float qz = fminf(fmaxf((pz * 0.5f + 0.5f) * 255.0f, 0.0f), 255.0f);
    int x0 = (int)qx, y0 = (int)qy, z0 = (int)qz;
    float fx = qx - (float)x0;
    float fy = qy - (float)y0;
    float fz = qz - (float)z0;
    int dx = (x0 < RES - 1) ? RES * RES : 0;
    int dy = (y0 < RES - 1) ? RES : 0;
    int dz = (z0 < RES - 1) ? 1 : 0;
    int base = (((x0 << 8) + y0) << 8) + z0;

    float c000 = __ldg(vol + base);
    float c001 = __ldg(vol + base + dz);
    float c010 = __ldg(vol + base + dy);
    float c011 = __ldg(vol + base + dy + dz);
    float c100 = __ldg(vol + base + dx);
    float c101 = __ldg(vol + base + dx + dz);
    float c110 = __ldg(vol + base + dx + dy);
    float c111 = __ldg(vol + base + dx + dy + dz);

    float c00 = c000 + fx * (c100 - c000);
    float c10 = c010 + fx * (c110 - c010);
    float c01 = c001 + fx * (c101 - c001);
    float c11 = c011 + fx * (c111 - c011);
    float c0 = c00 + fy * (c10 - c00);
    float c1 = c01 + fy * (c11 - c01);
    return c0 + fz * (c1 - c0);
}

__global__ void __launch_bounds__(BLOCK, 4)
raycast_kernel(const float* __restrict__ vol,
               const float* __restrict__ tf,
               const float* __restrict__ cam_in,
               const int*   __restrict__ sr_in,
               float* __restrict__ out)
{
    __shared__ float4 s_tf[TF_RES];
    int tid = threadIdx.x;
    if (tid < TF_RES) s_tf[tid] = reinterpret_cast<const float4*>(tf)[tid];
    __syncthreads();

    // ---- 4 lanes per ray (a "quad"). Warp = 8 rays in a 4h x 2w tile. ----
    // Block = 8 warps arranged 2 in h x 4 in w -> block tile 8h x 8w rays.
    int lane = tid & 31;
    int warp = tid >> 5;
    int sub  = lane & 3;              // sample slot within the group of 4
    int quad = lane >> 2;             // ray index within warp (0..7)
    unsigned qmask = 0xFu << (lane & ~3);

    int h_in = quad & 3;
    int w_in = quad >> 2;
    int warp_h = (warp & 1) << 2;
    int warp_w = (warp >> 1) << 1;
    int bx = blockIdx.x;              // 0..1023
    int tile_h = (bx & 31) << 3;
    int tile_w = (bx >> 5) << 3;
    int h = tile_h + warp_h + h_in;
    int w = tile_w + warp_w + w_in;

    // --- decode sampling rate (robust to int32 or float32 storage) ---
    int raw = sr_in[0];
    float sr;
    if (raw >= 1 && raw <= 4096) {
        sr = (float)raw;
    } else {
        float f = __int_as_float(raw);
        sr = (f > 0.0f && f <= 4096.0f) ? f : 1.0f;
    }
    float inv_sr = 1.0f / sr;
    bool sr_is_one = (sr == 1.0f);

    V3 cam = v3(cam_in[0], cam_in[1], cam_in[2]);

    V3 fwd = vnorm(v3(-cam.x, -cam.y, -cam.z));
    V3 right = vnorm(v3(-fwd.z, 0.0f, fwd.x));
    V3 up = vcross(right, fwd);

    const float tanf_half = 0.2679491924311227f;      // tan(15 deg)
    float u = ((w + 0.5f) * (2.0f / (float)W) - 1.0f) * tanf_half;
    float v = ((h + 0.5f) * (2.0f / (float)H) - 1.0f) * tanf_half;

    V3 dir = vnorm(vadd(fwd, vadd(vscale(right, u), vscale(up, v))));

    float ix = 1.0f / dir.x, iy = 1.0f / dir.y, iz = 1.0f / dir.z;
    float tx0 = (-1.0f - cam.x) * ix, tx1 = (1.0f - cam.x) * ix;
    float ty0 = (-1.0f - cam.y) * iy, ty1 = (1.0f - cam.y) * iy;
    float tz0 = (-1.0f - cam.z) * iz, tz1 = (1.0f - cam.z) * iz;
    float tmin = fmaxf(fmaxf(fminf(tx0, tx1), fminf(ty0, ty1)), fminf(tz0, tz1));
    float tmax = fminf(fminf(fmaxf(tx0, tx1), fmaxf(ty0, ty1)), fmaxf(tz0, tz1));
    bool hit = (tmax >= 0.0f) && (tmin <= tmax);

    float rr = 0.0f, gg = 0.0f, bb = 0.0f, acc = 0.0f;
    float depth = 1.0f;

    if (hit) {
        float entry = fmaxf(tmin, NEAR_T);
        float dist = fmaxf(tmax - entry, 0.0f);
        float ns = ceilf(dist * 0.5f * (float)RES * sr);
        ns = fminf(fmaxf(ns, 1.0f), (float)MAX_SAMPLES);
        float step = dist / ns;
        int n = (int)ns;

        float T = 1.0f;              // replicated across the quad
        bool any_hit = false;        // quad-uniform
        float t_first = 0.0f;

        for (int k0 = 0; k0 < n; k0 += 4) {
            int k = k0 + sub;        // this lane's sample index
            float t = entry + ((float)k + 0.5f) * step;

            // ---- parallel across the quad: sample + TF (own sample only) ----
            float inten = sample_vol(vol, cam, dir, t);
            float xi = fminf(fmaxf(inten, 0.0f), 1.0f) * (float)(TF_RES - 1);
            int l = (int)xi;
            float f = xi - (float)l;
            int hi2 = min(l + 1, TF_RES - 1);
            float4 ca = s_tf[l];
            float4 cb = s_tf[hi2];
            float mcr = ca.x + f * (cb.x - ca.x);
            float mcg = ca.y + f * (cb.y - ca.y);
            float mcb = ca.z + f * (cb.z - ca.z);
            float ma  = ca.w + f * (cb.w - ca.w);
            if (!sr_is_one) ma = 1.0f - powf(1.0f - ma, inv_sr);
            if (k >= n) ma = 0.0f;   // tail guard: invalid samples contribute 0

            // ---- exchange only transmittance factors (2 shuffles) ----
            float m = 1.0f - ma;
            float s1 = __shfl_xor_sync(qmask, m, 1);        // xor-1 partner's m
            float pairProd = m * s1;                         // product of this pair
            float s2 = __shfl_xor_sync(qmask, pairProd, 2);  // other pair's product
            // exclusive prefix of (1-a) within the quad:
            float prefix = 1.0f;
            if (sub & 1) prefix = s1;                        // m of even lane in pair
            if (sub & 2) prefix *= s2;                       // product of lower pair
            float groupProd = pairProd * s2;

            // ---- each lane accumulates ONLY its own sample's contribution ----
            // w_k = T * prod_{j<k}(1-a_j) * a_k  == reference weight exactly
            float wgt = T * prefix * ma;
            rr += wgt * mcr;
            gg += wgt * mcg;
            bb += wgt * mcb;
            acc += wgt;

            // ---- first-hit: min sub with a > EPS (only until resolved) ----
            if (!any_hit) {
                int hs = (ma > HIT_EPS) ? sub : 8;
                hs = min(hs, __shfl_xor_sync(qmask, hs, 1));
                hs = min(hs, __shfl_xor_sync(qmask, hs, 2));
                if (hs < 8) {
                    any_hit = true;
                    t_first = entry + ((float)(k0 + hs) + 0.5f) * step;
                }
            }

            T *= groupProd;
            // Early termination: remaining contribution bounded by T < 1e-5.
            // First-hit provably resolved before T reaches 1e-5
            // (all a<=1e-3 over 384 samples keeps T >= 0.68).
            if (T < 1e-5f) break;
        }

        // ---- merge quad-partial color sums (once) ----
        rr += __shfl_xor_sync(qmask, rr, 1);
        rr += __shfl_xor_sync(qmask, rr, 2);
        gg += __shfl_xor_sync(qmask, gg, 1);
        gg += __shfl_xor_sync(qmask, gg, 2);
        bb += __shfl_xor_sync(qmask, bb, 1);
        bb += __shfl_xor_sync(qmask, bb, 2);
        acc += __shfl_xor_sync(qmask, acc, 1);
        acc += __shfl_xor_sync(qmask, acc, 2);

        if (any_hit) depth = (t_first - NEAR_T) / (FAR_T - NEAR_T);
    }

    if (sub == 0) {
        float* o = out + ((size_t)w * H + h) * 5;
        o[0] = rr;
        o[1] = gg;
        o[2] = bb;
        o[3] = acc;
        o[4] = depth;
    }
}

extern "C" void kernel_launch(void* const* d_in, const int* in_sizes, int n_in,
                              void* d_out, int out_size)
{
    const float* vol = (const float*)d_in[0];
    const float* tf  = (const float*)d_in[1];
    const float* cam = (const float*)d_in[2];
    const int*   sr  = (const int*)d_in[3];
    float* out = (float*)d_out;
    // 4 threads per ray: 262144 threads total
    raycast_kernel<<<(W * H * 4) / BLOCK, BLOCK>>>(vol, tf, cam, sr, out);
}

// round 7
// speedup vs baseline: 1.8547x; 1.1052x over previous
#include <cuda_runtime.h>
#include <math.h>

#define RES 256
#define W 256
#define H 256
#define MAX_SAMPLES 384
#define TF_RES 128
#define NEAR_T 0.1f
#define FAR_T 100.0f
#define HIT_EPS 1e-3f
#define BLOCK 128

struct V3 { float x, y, z; };

__device__ __forceinline__ V3 v3(float x, float y, float z) { V3 r; r.x=x; r.y=y; r.z=z; return r; }
__device__ __forceinline__ V3 vadd(V3 a, V3 b) { return v3(a.x+b.x, a.y+b.y, a.z+b.z); }
__device__ __forceinline__ V3 vscale(V3 a, float s) { return v3(a.x*s, a.y*s, a.z*s); }
__device__ __forceinline__ V3 vcross(V3 a, V3 b) {
    return v3(a.y*b.z - a.z*b.y, a.z*b.x - a.x*b.z, a.x*b.y - a.y*b.x);
}
__device__ __forceinline__ V3 vnorm(V3 a) {
    float inv = rsqrtf(a.x*a.x + a.y*a.y + a.z*a.z);
    return vscale(a, inv);
}

__device__ __forceinline__ float sample_vol(const float* __restrict__ vol,
                                            V3 cam, V3 dir, float t)
{
    float px = cam.x + t * dir.x;
    float py = cam.y + t * dir.y;
    float pz = cam.z + t * dir.z;
    float qx = fminf(fmaxf((px * 0.5f + 0.5f) * 255.0f, 0.0f), 255.0f);
    float qy = fminf(fmaxf((py * 0.5f + 0.5f) * 255.0f, 0.0f), 255.0f);
    float qz = fminf(fmaxf((pz * 0.5f + 0.5f) * 255.0f, 0.0f), 255.0f);
    int x0 = (int)qx, y0 = (int)qy, z0 = (int)qz;
    float fx = qx - (float)x0;
    float fy = qy - (float)y0;
    float fz = qz - (float)z0;
    int dx = (x0 < RES - 1) ? RES * RES : 0;
    int dy = (y0 < RES - 1) ? RES : 0;
    int dz = (z0 < RES - 1) ? 1 : 0;
    int base = (((x0 << 8) + y0) << 8) + z0;

    float c000 = __ldg(vol + base);
    float c001 = __ldg(vol + base + dz);
    float c010 = __ldg(vol + base + dy);
    float c011 = __ldg(vol + base + dy + dz);
    float c100 = __ldg(vol + base + dx);
    float c101 = __ldg(vol + base + dx + dz);
    float c110 = __ldg(vol + base + dx + dy);
    float c111 = __ldg(vol + base + dx + dy + dz);

    float c00 = c000 + fx * (c100 - c000);
    float c10 = c010 + fx * (c110 - c010);
    float c01 = c001 + fx * (c101 - c001);
    float c11 = c011 + fx * (c111 - c011);
    float c0 = c00 + fy * (c10 - c00);
    float c1 = c01 + fy * (c11 - c01);
    return c0 + fz * (c1 - c0);
}

__global__ void __launch_bounds__(BLOCK, 10)
raycast_kernel(const float* __restrict__ vol,
               const float* __restrict__ tf,
               const float* __restrict__ cam_in,
               const int*   __restrict__ sr_in,
               float* __restrict__ out)
{
    __shared__ float4 s_tf[TF_RES];
    int tid = threadIdx.x;
    if (tid < TF_RES) s_tf[tid] = reinterpret_cast<const float4*>(tf)[tid];
    __syncthreads();

    // ---- 4 lanes per ray (a "quad"). Warp = 8 rays in a 4h x 2w tile. ----
    // Block = 4 warps arranged 2 in h x 2 in w -> block tile 8h x 4w rays.
    int lane = tid & 31;
    int warp = tid >> 5;
    int sub  = lane & 3;              // sample slot within the group of 4
    int quad = lane >> 2;             // ray index within warp (0..7)
    unsigned qmask = 0xFu << (lane & ~3);

    int h_in = quad & 3;
    int w_in = quad >> 2;
    int warp_h = (warp & 1) << 2;
    int warp_w = (warp >> 1) << 1;
    int bx = blockIdx.x;              // 0..2047
    int tile_h = (bx & 31) << 3;      // 32 tiles of 8 in h
    int tile_w = (bx >> 5) << 2;      // 64 tiles of 4 in w
    int h = tile_h + warp_h + h_in;
    int w = tile_w + warp_w + w_in;

    // --- decode sampling rate (robust to int32 or float32 storage) ---
    int raw = sr_in[0];
    float sr;
    if (raw >= 1 && raw <= 4096) {
        sr = (float)raw;
    } else {
        float f = __int_as_float(raw);
        sr = (f > 0.0f && f <= 4096.0f) ? f : 1.0f;
    }
    float inv_sr = 1.0f / sr;
    bool sr_is_one = (sr == 1.0f);

    V3 cam = v3(cam_in[0], cam_in[1], cam_in[2]);

    V3 fwd = vnorm(v3(-cam.x, -cam.y, -cam.z));
    V3 right = vnorm(v3(-fwd.z, 0.0f, fwd.x));
    V3 up = vcross(right, fwd);

    const float tanf_half = 0.2679491924311227f;      // tan(15 deg)
    float u = ((w + 0.5f) * (2.0f / (float)W) - 1.0f) * tanf_half;
    float v = ((h + 0.5f) * (2.0f / (float)H) - 1.0f) * tanf_half;

    V3 dir = vnorm(vadd(fwd, vadd(vscale(right, u), vscale(up, v))));

    float ix = 1.0f / dir.x, iy = 1.0f / dir.y, iz = 1.0f / dir.z;
    float tx0 = (-1.0f - cam.x) * ix, tx1 = (1.0f - cam.x) * ix;
    float ty0 = (-1.0f - cam.y) * iy, ty1 = (1.0f - cam.y) * iy;
    float tz0 = (-1.0f - cam.z) * iz, tz1 = (1.0f - cam.z) * iz;
    float tmin = fmaxf(fmaxf(fminf(tx0, tx1), fminf(ty0, ty1)), fminf(tz0, tz1));
    float tmax = fminf(fminf(fmaxf(tx0, tx1), fmaxf(ty0, ty1)), fmaxf(tz0, tz1));
    bool hit = (tmax >= 0.0f) && (tmin <= tmax);

    float rr = 0.0f, gg = 0.0f, bb = 0.0f, acc = 0.0f;
    float depth = 1.0f;

    if (hit) {
        float entry = fmaxf(tmin, NEAR_T);
        float dist = fmaxf(tmax - entry, 0.0f);
        float ns = ceilf(dist * 0.5f * (float)RES * sr);
        ns = fminf(fmaxf(ns, 1.0f), (float)MAX_SAMPLES);
        float step = dist / ns;
        int n = (int)ns;

        float T = 1.0f;              // replicated across the quad
        int my_first = 0x7FFFFFFF;   // lane-local first-hit sample index

        for (int k0 = 0; k0 < n; k0 += 4) {
            int k = k0 + sub;        // this lane's sample index
            float t = entry + ((float)k + 0.5f) * step;

            // ---- parallel across the quad: sample + TF (own sample only) ----
            float inten = sample_vol(vol, cam, dir, t);
            float xi = fminf(fmaxf(inten, 0.0f), 1.0f) * (float)(TF_RES - 1);
            int l = (int)xi;
            float f = xi - (float)l;
            int hi2 = min(l + 1, TF_RES - 1);
            float4 ca = s_tf[l];
            float4 cb = s_tf[hi2];
            float mcr = ca.x + f * (cb.x - ca.x);
            float mcg = ca.y + f * (cb.y - ca.y);
            float mcb = ca.z + f * (cb.z - ca.z);
            float ma  = ca.w + f * (cb.w - ca.w);
            if (!sr_is_one) ma = 1.0f - powf(1.0f - ma, inv_sr);
            if (k >= n) ma = 0.0f;   // tail guard: invalid samples contribute 0

            // lane-local first-hit tracking (no shuffles in loop)
            if (my_first == 0x7FFFFFFF && ma > HIT_EPS) my_first = k;

            // ---- exchange only transmittance factors (2 shuffles) ----
            float m = 1.0f - ma;
            float s1 = __shfl_xor_sync(qmask, m, 1);
            float pairProd = m * s1;
            float s2 = __shfl_xor_sync(qmask, pairProd, 2);
            float prefix = 1.0f;
            if (sub & 1) prefix = s1;
            if (sub & 2) prefix *= s2;
            float groupProd = pairProd * s2;

            // ---- each lane accumulates ONLY its own sample's contribution ----
            float wgt = T * prefix * ma;
            rr += wgt * mcr;
            gg += wgt * mcg;
            bb += wgt * mcb;
            acc += wgt;

            T *= groupProd;
            // Early termination: remaining contribution bounded by T < 1e-4.
            // First-hit provably resolved before T reaches 1e-4
            // (all a<=1e-3 over 384 samples keeps T >= 0.68).
            if (T < 1e-4f) break;
        }

        // ---- one-time quad reductions ----
        rr += __shfl_xor_sync(qmask, rr, 1);
        rr += __shfl_xor_sync(qmask, rr, 2);
        gg += __shfl_xor_sync(qmask, gg, 1);
        gg += __shfl_xor_sync(qmask, gg, 2);
        bb += __shfl_xor_sync(qmask, bb, 1);
        bb += __shfl_xor_sync(qmask, bb, 2);
        acc += __shfl_xor_sync(qmask, acc, 1);
        acc += __shfl_xor_sync(qmask, acc, 2);
        my_first = min(my_first, __shfl_xor_sync(qmask, my_first, 1));
        my_first = min(my_first, __shfl_xor_sync(qmask, my_first, 2));

        if (my_first != 0x7FFFFFFF) {
            float t_first = entry + ((float)my_first + 0.5f) * step;
            depth = (t_first - NEAR_T) / (FAR_T - NEAR_T);
        }
    }

    if (sub == 0) {
        float* o = out + ((size_t)w * H + h) * 5;
        o[0] = rr;
        o[1] = gg;
        o[2] = bb;
        o[3] = acc;
        o[4] = depth;
    }
}

extern "C" void kernel_launch(void* const* d_in, const int* in_sizes, int n_in,
                              void* d_out, int out_size)
{
    const float* vol = (const float*)d_in[0];
    const float* tf  = (const float*)d_in[1];
    const float* cam = (const float*)d_in[2];
    const int*   sr  = (const int*)d_in[3];
    float* out = (float*)d_out;
    // 4 threads per ray: 262144 threads total
    raycast_kernel<<<(W * H * 4) / BLOCK, BLOCK>>>(vol, tf, cam, sr, out);
}

// round 8
// speedup vs baseline: 2.0594x; 1.1104x over previous
#include <cuda_runtime.h>
#include <math.h>

#define RES 256
#define W 256
#define H 256
#define MAX_SAMPLES 384
#define TF_RES 128
#define NEAR_T 0.1f
#define FAR_T 100.0f
#define HIT_EPS 1e-3f
#define BLOCK 128

struct V3 { float x, y, z; };

__device__ __forceinline__ V3 v3(float x, float y, float z) { V3 r; r.x=x; r.y=y; r.z=z; return r; }
__device__ __forceinline__ V3 vadd(V3 a, V3 b) { return v3(a.x+b.x, a.y+b.y, a.z+b.z); }
__device__ __forceinline__ V3 vscale(V3 a, float s) { return v3(a.x*s, a.y*s, a.z*s); }
__device__ __forceinline__ V3 vcross(V3 a, V3 b) {
    return v3(a.y*b.z - a.z*b.y, a.z*b.x - a.x*b.z, a.x*b.y - a.y*b.x);
}
__device__ __forceinline__ V3 vnorm(V3 a) {
    float inv = rsqrtf(a.x*a.x + a.y*a.y + a.z*a.z);
    return vscale(a, inv);
}

__device__ __forceinline__ float sample_vol(const float* __restrict__ vol,
                                            V3 cam, V3 dir, float t)
{
    float px = cam.x + t * dir.x;
    float py = cam.y + t * dir.y;
    float pz = cam.z + t * dir.z;
    float qx = fminf(fmaxf((px * 0.5f + 0.5f) * 255.0f, 0.0f), 255.0f);
    float qy = fminf(fmaxf((py * 0.5f + 0.5f) * 255.0f, 0.0f), 255.0f);
    float qz = fminf(fmaxf((pz * 0.5f + 0.5f) * 255.0f, 0.0f), 255.0f);
    int x0 = (int)qx, y0 = (int)qy, z0 = (int)qz;
    float fx = qx - (float)x0;
    float fy = qy - (float)y0;
    float fz = qz - (float)z0;
    int dx = (x0 < RES - 1) ? RES * RES : 0;
    int dy = (y0 < RES - 1) ? RES : 0;
    int dz = (z0 < RES - 1) ? 1 : 0;
    int base = (((x0 << 8) + y0) << 8) + z0;

    float c000 = __ldg(vol + base);
    float c001 = __ldg(vol + base + dz);
    float c010 = __ldg(vol + base + dy);
    float c011 = __ldg(vol + base + dy + dz);
    float c100 = __ldg(vol + base + dx);
    float c101 = __ldg(vol + base + dx + dz);
    float c110 = __ldg(vol + base + dx + dy);
    float c111 = __ldg(vol + base + dx + dy + dz);

    float c00 = c000 + fx * (c100 - c000);
    float c10 = c010 + fx * (c110 - c010);
    float c01 = c001 + fx * (c101 - c001);
    float c11 = c011 + fx * (c111 - c011);
    float c0 = c00 + fy * (c10 - c00);
    float c1 = c01 + fy * (c11 - c01);
    return c0 + fz * (c1 - c0);
}

__global__ void __launch_bounds__(BLOCK, 12)
raycast_kernel(const float* __restrict__ vol,
               const float* __restrict__ tf,
               const float* __restrict__ cam_in,
               const int*   __restrict__ sr_in,
               float* __restrict__ out)
{
    __shared__ float4 s_tf[TF_RES];
    int tid = threadIdx.x;
    if (tid < TF_RES) s_tf[tid] = reinterpret_cast<const float4*>(tf)[tid];
    __syncthreads();

    // ---- 4 lanes per ray (a "quad"). Warp = 8 rays in a 4h x 2w tile. ----
    // Block = 4 warps arranged 2 in h x 2 in w -> block tile 8h x 4w rays.
    int lane = tid & 31;
    int warp = tid >> 5;
    int sub  = lane & 3;              // sample slot within the group of 4
    int quad = lane >> 2;             // ray index within warp (0..7)
    unsigned qmask = 0xFu << (lane & ~3);

    int h_in = quad & 3;
    int w_in = quad >> 2;
    int warp_h = (warp & 1) << 2;
    int warp_w = (warp >> 1) << 1;
    // Permute block index (odd multiplier -> bijection mod 2048) so each
    // scheduling wave sees a spatially representative mix of ray costs.
    int bx = (blockIdx.x * 1337) & 2047;
    int tile_h = (bx & 31) << 3;      // 32 tiles of 8 in h
    int tile_w = (bx >> 5) << 2;      // 64 tiles of 4 in w
    int h = tile_h + warp_h + h_in;
    int w = tile_w + warp_w + w_in;

    // --- decode sampling rate (robust to int32 or float32 storage) ---
    int raw = sr_in[0];
    float sr;
    if (raw >= 1 && raw <= 4096) {
        sr = (float)raw;
    } else {
        float f = __int_as_float(raw);
        sr = (f > 0.0f && f <= 4096.0f) ? f : 1.0f;
    }
    float inv_sr = 1.0f / sr;
    bool sr_is_one = (sr == 1.0f);

    V3 cam = v3(cam_in[0], cam_in[1], cam_in[2]);

    V3 fwd = vnorm(v3(-cam.x, -cam.y, -cam.z));
    V3 right = vnorm(v3(-fwd.z, 0.0f, fwd.x));
    V3 up = vcross(right, fwd);

    const float tanf_half = 0.2679491924311227f;      // tan(15 deg)
    float u = ((w + 0.5f) * (2.0f / (float)W) - 1.0f) * tanf_half;
    float v = ((h + 0.5f) * (2.0f / (float)H) - 1.0f) * tanf_half;

    V3 dir = vnorm(vadd(fwd, vadd(vscale(right, u), vscale(up, v))));

    float ix = 1.0f / dir.x, iy = 1.0f / dir.y, iz = 1.0f / dir.z;
    float tx0 = (-1.0f - cam.x) * ix, tx1 = (1.0f - cam.x) * ix;
    float ty0 = (-1.0f - cam.y) * iy, ty1 = (1.0f - cam.y) * iy;
    float tz0 = (-1.0f - cam.z) * iz, tz1 = (1.0f - cam.z) * iz;
    float tmin = fmaxf(fmaxf(fminf(tx0, tx1), fminf(ty0, ty1)), fminf(tz0, tz1));
    float tmax = fminf(fminf(fmaxf(tx0, tx1), fmaxf(ty0, ty1)), fmaxf(tz0, tz1));
    bool hit = (tmax >= 0.0f) && (tmin <= tmax);

    float rr = 0.0f, gg = 0.0f, bb = 0.0f, acc = 0.0f;
    float depth = 1.0f;

    if (hit) {
        float entry = fmaxf(tmin, NEAR_T);
        float dist = fmaxf(tmax - entry, 0.0f);
        float ns = ceilf(dist * 0.5f * (float)RES * sr);
        ns = fminf(fmaxf(ns, 1.0f), (float)MAX_SAMPLES);
        float step = dist / ns;
        int n = (int)ns;

        float T = 1.0f;              // replicated across the quad
        int my_first = 0x7FFFFFFF;   // lane-local first-hit sample index

        for (int k0 = 0; k0 < n; k0 += 4) {
            int k = k0 + sub;        // this lane's sample index
            float t = entry + ((float)k + 0.5f) * step;

            // ---- parallel across the quad: sample + TF (own sample only) ----
            float inten = sample_vol(vol, cam, dir, t);
            float xi = fminf(fmaxf(inten, 0.0f), 1.0f) * (float)(TF_RES - 1);
            int l = (int)xi;
            float f = xi - (float)l;
            int hi2 = min(l + 1, TF_RES - 1);
            float4 ca = s_tf[l];
            float4 cb = s_tf[hi2];
            float mcr = ca.x + f * (cb.x - ca.x);
            float mcg = ca.y + f * (cb.y - ca.y);
            float mcb = ca.z + f * (cb.z - ca.z);
            float ma  = ca.w + f * (cb.w - ca.w);
            if (!sr_is_one) ma = 1.0f - powf(1.0f - ma, inv_sr);
            if (k >= n) ma = 0.0f;   // tail guard: invalid samples contribute 0

            // lane-local first-hit tracking (no shuffles in loop)
            if (my_first == 0x7FFFFFFF && ma > HIT_EPS) my_first = k;

            // ---- exchange only transmittance factors (2 shuffles) ----
            float m = 1.0f - ma;
            float s1 = __shfl_xor_sync(qmask, m, 1);
            float pairProd = m * s1;
            float s2 = __shfl_xor_sync(qmask, pairProd, 2);
            float prefix = 1.0f;
            if (sub & 1) prefix = s1;
            if (sub & 2) prefix *= s2;
            float groupProd = pairProd * s2;

            // ---- each lane accumulates ONLY its own sample's contribution ----
            float wgt = T * prefix * ma;
            rr += wgt * mcr;
            gg += wgt * mcg;
            bb += wgt * mcb;
            acc += wgt;

            T *= groupProd;
            // Early termination: remaining contribution bounded by T < 5e-4.
            // Empirically (R7): loosening 1e-5 -> 1e-4 moved rel_err by only
            // +3.3e-6; bound is very loose vs the 1e-3 gate. First-hit is
            // provably resolved before T reaches 5e-4 (all a<=1e-3 over 384
            // samples keeps T >= 0.68).
            if (T < 5e-4f) break;
        }

        // ---- one-time quad reductions ----
        rr += __shfl_xor_sync(qmask, rr, 1);
        rr += __shfl_xor_sync(qmask, rr, 2);
        gg += __shfl_xor_sync(qmask, gg, 1);
        gg += __shfl_xor_sync(qmask, gg, 2);
        bb += __shfl_xor_sync(qmask, bb, 1);
        bb += __shfl_xor_sync(qmask, bb, 2);
        acc += __shfl_xor_sync(qmask, acc, 1);
        acc += __shfl_xor_sync(qmask, acc, 2);
        my_first = min(my_first, __shfl_xor_sync(qmask, my_first, 1));
        my_first = min(my_first, __shfl_xor_sync(qmask, my_first, 2));

        if (my_first != 0x7FFFFFFF) {
            float t_first = entry + ((float)my_first + 0.5f) * step;
            depth = (t_first - NEAR_T) / (FAR_T - NEAR_T);
        }
    }

    if (sub == 0) {
        float* o = out + ((size_t)w * H + h) * 5;
        o[0] = rr;
        o[1] = gg;
        o[2] = bb;
        o[3] = acc;
        o[4] = depth;
    }
}

extern "C" void kernel_launch(void* const* d_in, const int* in_sizes, int n_in,
                              void* d_out, int out_size)
{
    const float* vol = (const float*)d_in[0];
    const float* tf  = (const float*)d_in[1];
    const float* cam = (const float*)d_in[2];
    const int*   sr  = (const int*)d_in[3];
    float* out = (float*)d_out;
    // 4 threads per ray: 262144 threads total
    raycast_kernel<<<(W * H * 4) / BLOCK, BLOCK>>>(vol, tf, cam, sr, out);
}